// round 12
// baseline (speedup 1.0000x reference)
#include <cuda_runtime.h>
#include <cuda.h>
#include <cstdint>

// Problem constants
#define BATCH 32
#define NQ    512
#define HD    1024
#define OD    1024
#define NSUBJ 8

// Tiling: CTA 128x128, 4 warps each 64x64; K split in 2 halves of 16 chunks
#define BM 128
#define BN 128
#define BKF 32
#define CHUNKS_H 16          // chunks per K-half
#define NST 3
#define THREADS 128
#define NTILES (8 * 4 * 32)  // n-tiles * m-tiles * batch = 1024

// SMEM layout
#define SMB_FULL(s)  ((s) * 8)
#define SMB_EMPTY(s) (24 + (s) * 8)
#define SM_A(s)      (1024 + (s) * 32768)
#define SM_B(s)      (SM_A(s) + 16384)
#define STAGE_BYTES  32768
#define SMEM_TOTAL   (1024 + NST * STAGE_BYTES)   // 99328

// Split-K scratch: per-tile fp32 partial (kv=0 half) + ready flags
__device__ float g_part[(size_t)NTILES * BM * BN];   // 64 MB
__device__ int   g_flag[NTILES];

__device__ __forceinline__ uint32_t smem_u32(const void* p) {
    return (uint32_t)__cvta_generic_to_shared(p);
}
__device__ __forceinline__ void mbar_init(uint32_t a, uint32_t cnt) {
    asm volatile("mbarrier.init.shared.b64 [%0], %1;" :: "r"(a), "r"(cnt) : "memory");
}
__device__ __forceinline__ void mbar_expect_tx(uint32_t a, uint32_t bytes) {
    asm volatile("mbarrier.arrive.expect_tx.shared.b64 _, [%0], %1;"
                 :: "r"(a), "r"(bytes) : "memory");
}
__device__ __forceinline__ void mbar_arrive(uint32_t a) {
    asm volatile("mbarrier.arrive.shared.b64 _, [%0];" :: "r"(a) : "memory");
}
__device__ __forceinline__ void mbar_wait(uint32_t a, uint32_t parity) {
    asm volatile(
        "{\n\t.reg .pred P;\n"
        "WL%=:\n\tmbarrier.try_wait.parity.shared.b64 P, [%0], %1;\n"
        "\t@P bra WD%=;\n\tbra WL%=;\nWD%=:\n\t}"
        :: "r"(a), "r"(parity) : "memory");
}
__device__ __forceinline__ void tma_load_3d(uint32_t dst, const CUtensorMap* tm,
                                            int cx, int cy, int cz, uint32_t mbar) {
    asm volatile(
        "cp.async.bulk.tensor.3d.shared::cta.global.tile.mbarrier::complete_tx::bytes "
        "[%0], [%1, {%2, %3, %4}], [%5];"
        :: "r"(dst), "l"(tm), "r"(cx), "r"(cy), "r"(cz), "r"(mbar) : "memory");
}
__device__ __forceinline__ uint32_t f2tf32(float f) {
    uint32_t r;
    asm("cvt.rna.tf32.f32 %0, %1;\n" : "=r"(r) : "f"(f));
    return r;
}

// ---------------- flag init (runs every launch; graph-replay safe) ----------
__global__ void __launch_bounds__(256) init_flags() {
    const int i = blockIdx.x * blockDim.x + threadIdx.x;
    if (i < NTILES) g_flag[i] = 0;
}

// ---------------- main split-K GEMM ----------------
__global__ __launch_bounds__(THREADS, 2)
void scl_tf32_v9(const __grid_constant__ CUtensorMap tma_x,
                 const __grid_constant__ CUtensorMap tma_w,
                 const int*   __restrict__ sid,
                 const float* __restrict__ bias,
                 float*       __restrict__ y) {
    extern __shared__ char smem[];
    const uint32_t sb = smem_u32(smem);

    const int kv = blockIdx.x;                 // 0: low K half, 1: high K half
    const int n0 = blockIdx.y * BN;            // O tile
    const int mz = blockIdx.z;
    const int m0 = (mz & 3) * BM;              // N (query) tile
    const int b  = mz >> 2;                    // batch
    const int tidx = blockIdx.y + (mz << 3);   // 0..1023
    const int cbase = kv * CHUNKS_H;

    const int s  = __ldg(&sid[b]);

    const int tid  = threadIdx.x;
    const int wid  = tid >> 5;
    const int lane = tid & 31;
    const int g    = lane >> 2;
    const int tg   = lane & 3;
    const int gx   = g << 2;            // SW128 XOR (word units)
    const int wm   = (wid & 1) * 64;
    const int wn   = (wid >> 1) * 64;

    if (tid == 0) {
        for (int st = 0; st < NST; st++) {
            mbar_init(sb + SMB_FULL(st), 1);
            mbar_init(sb + SMB_EMPTY(st), 4);
        }
    }
    __syncthreads();
    if (tid == 0) {
        for (int c = 0; c < NST; c++) {
            mbar_expect_tx(sb + SMB_FULL(c), STAGE_BYTES);
            tma_load_3d(sb + SM_A(c), &tma_x, (cbase + c) * BKF, m0, b, sb + SMB_FULL(c));
            tma_load_3d(sb + SM_B(c), &tma_w, (cbase + c) * BKF, n0, s, sb + SMB_FULL(c));
        }
    }

    float acc[4][8][4];
    #pragma unroll
    for (int i = 0; i < 4; i++)
        #pragma unroll
        for (int j = 0; j < 8; j++)
            #pragma unroll
            for (int k = 0; k < 4; k++) acc[i][j][k] = 0.f;

    uint32_t af0[4][4], bf0[8][2];
    uint32_t af1[4][4], bf1[8][2];

    // A (x): raw fp32 (HW truncates to tf32). B (W): RNA in-register.
    auto ldfrag = [&](uint32_t af[4][4], uint32_t bf[8][2],
                      const float* A, const float* Bsm, int kl) {
        const int c0k = (kl + tg) ^ gx;
        const int c1k = (kl + tg + 4) ^ gx;
        #pragma unroll
        for (int mi = 0; mi < 4; mi++) {
            const int r0 = wm + mi * 16 + g;
            af[mi][0] = __float_as_uint(A[ r0      * 32 + c0k]);
            af[mi][1] = __float_as_uint(A[(r0 + 8) * 32 + c0k]);
            af[mi][2] = __float_as_uint(A[ r0      * 32 + c1k]);
            af[mi][3] = __float_as_uint(A[(r0 + 8) * 32 + c1k]);
        }
        #pragma unroll
        for (int ni = 0; ni < 8; ni++) {
            const int c0 = wn + ni * 8 + g;
            bf[ni][0] = f2tf32(Bsm[c0 * 32 + c0k]);
            bf[ni][1] = f2tf32(Bsm[c0 * 32 + c1k]);
        }
    };

    auto domma = [&](uint32_t af[4][4], uint32_t bf[8][2]) {
        #pragma unroll
        for (int mi = 0; mi < 4; mi++)
            #pragma unroll
            for (int ni = 0; ni < 8; ni++) {
                asm volatile(
                    "mma.sync.aligned.m16n8k8.row.col.f32.tf32.tf32.f32 "
                    "{%0,%1,%2,%3}, {%4,%5,%6,%7}, {%8,%9}, {%0,%1,%2,%3};\n"
                    : "+f"(acc[mi][ni][0]), "+f"(acc[mi][ni][1]),
                      "+f"(acc[mi][ni][2]), "+f"(acc[mi][ni][3])
                    : "r"(af[mi][0]), "r"(af[mi][1]),
                      "r"(af[mi][2]), "r"(af[mi][3]),
                      "r"(bf[ni][0]), "r"(bf[ni][1]));
            }
    };

    mbar_wait(sb + SMB_FULL(0), 0);
    ldfrag(af0, bf0, (const float*)(smem + SM_A(0)), (const float*)(smem + SM_B(0)), 0);

    int wp = 0;
    for (int kt = 0; kt < CHUNKS_H; kt++) {
        const int st = kt % NST;
        const float* A   = (const float*)(smem + SM_A(st));
        const float* Bsm = (const float*)(smem + SM_B(st));

        ldfrag(af1, bf1, A, Bsm, 8);
        domma(af0, bf0);
        ldfrag(af0, bf0, A, Bsm, 16);
        domma(af1, bf1);

        const int ns = (kt + 1) % NST;
        if (kt + 1 < CHUNKS_H) {
            if (ns == 0) wp ^= 1;
            mbar_wait(sb + SMB_FULL(ns), (uint32_t)wp);
        }

        ldfrag(af1, bf1, A, Bsm, 24);
        domma(af0, bf0);

        if (kt + 1 < CHUNKS_H)
            ldfrag(af0, bf0, (const float*)(smem + SM_A(ns)),
                             (const float*)(smem + SM_B(ns)), 0);
        domma(af1, bf1);

        if (lane == 0) mbar_arrive(sb + SMB_EMPTY(st));

        if (tid == 0 && kt + NST < CHUNKS_H) {
            mbar_wait(sb + SMB_EMPTY(st), (uint32_t)((kt / NST) & 1));
            mbar_expect_tx(sb + SMB_FULL(st), STAGE_BYTES);
            const int c = cbase + kt + NST;
            tma_load_3d(sb + SM_A(st), &tma_x, c * BKF, m0, b, sb + SMB_FULL(st));
            tma_load_3d(sb + SM_B(st), &tma_w, c * BKF, n0, s, sb + SMB_FULL(st));
        }
    }

    if (kv == 0) {
        // Producer: write partial (no bias), release flag.
        float* pp = g_part + (size_t)tidx * (BM * BN);
        #pragma unroll
        for (int mi = 0; mi < 4; mi++) {
            const int row = wm + mi * 16 + g;
            #pragma unroll
            for (int ni = 0; ni < 8; ni++) {
                const int col = wn + ni * 8 + tg * 2;
                *reinterpret_cast<float2*>(&pp[row * BN + col]) =
                    make_float2(acc[mi][ni][0], acc[mi][ni][1]);
                *reinterpret_cast<float2*>(&pp[(row + 8) * BN + col]) =
                    make_float2(acc[mi][ni][2], acc[mi][ni][3]);
            }
        }
        __threadfence();
        __syncthreads();
        if (tid == 0) {
            asm volatile("st.release.gpu.global.b32 [%0], %1;"
                         :: "l"(&g_flag[tidx]), "r"(1) : "memory");
        }
    } else {
        // Consumer: wait for partner's partial, then fuse + bias + store y.
        if (tid == 0) {
            int v = 0;
            do {
                asm volatile("ld.acquire.gpu.global.b32 %0, [%1];"
                             : "=r"(v) : "l"(&g_flag[tidx]) : "memory");
                if (!v) __nanosleep(128);
            } while (!v);
        }
        __syncthreads();

        const float* pp = g_part + (size_t)tidx * (BM * BN);
        const float* bb = bias + (size_t)s * OD + n0;
        float* yb = y + (size_t)b * NQ * OD + (size_t)m0 * OD + n0;

        #pragma unroll
        for (int mi = 0; mi < 4; mi++) {
            const int row = wm + mi * 16 + g;
            #pragma unroll
            for (int ni = 0; ni < 8; ni++) {
                const int col = wn + ni * 8 + tg * 2;
                const float b0v = __ldg(&bb[col]);
                const float b1v = __ldg(&bb[col + 1]);
                const float2 p0 = *reinterpret_cast<const float2*>(&pp[row * BN + col]);
                const float2 p1 = *reinterpret_cast<const float2*>(&pp[(row + 8) * BN + col]);
                float2 v0 = make_float2((p0.x + acc[mi][ni][0]) + b0v,
                                        (p0.y + acc[mi][ni][1]) + b1v);
                float2 v1 = make_float2((p1.x + acc[mi][ni][2]) + b0v,
                                        (p1.y + acc[mi][ni][3]) + b1v);
                *reinterpret_cast<float2*>(&yb[(size_t)row * OD + col])       = v0;
                *reinterpret_cast<float2*>(&yb[(size_t)(row + 8) * OD + col]) = v1;
            }
        }
    }
}

// ---------------- host launch ----------------
typedef int (*PFN_encodeTiled)(
    CUtensorMap*, int, unsigned int, void*,
    const unsigned long long*, const unsigned long long*,
    const unsigned int*, const unsigned int*,
    int, int, int, int);

extern "C" void kernel_launch(void* const* d_in, const int* in_sizes, int n_in,
                              void* d_out, int out_size) {
    const float* x    = (const float*)d_in[0];
    const int*   sid  = (const int*)  d_in[1];
    const float* w    = (const float*)d_in[2];
    const float* bias = (const float*)d_in[3];
    float* y = (float*)d_out;

    PFN_encodeTiled enc = nullptr;
    cudaDriverEntryPointQueryResult qr;
    cudaGetDriverEntryPoint("cuTensorMapEncodeTiled", (void**)&enc, cudaEnableDefault, &qr);

    // Enum ABI values: FLOAT32=7, interleave NONE=0, SWIZZLE_128B=3, L2_128B=2, OOB NONE=0
    CUtensorMap tx{}, tw{};
    {
        unsigned long long dims[3]    = {HD, NQ, BATCH};
        unsigned long long strides[2] = {HD * 4ull, (unsigned long long)NQ * HD * 4ull};
        unsigned int box[3]           = {BKF, BM, 1};
        unsigned int es[3]            = {1, 1, 1};
        enc(&tx, 7, 3, (void*)x, dims, strides, box, es, 0, 3, 2, 0);
    }
    {
        unsigned long long dims[3]    = {HD, OD, NSUBJ};
        unsigned long long strides[2] = {HD * 4ull, (unsigned long long)OD * HD * 4ull};
        unsigned int box[3]           = {BKF, BN, 1};
        unsigned int es[3]            = {1, 1, 1};
        enc(&tw, 7, 3, (void*)w, dims, strides, box, es, 0, 3, 2, 0);
    }

    cudaFuncSetAttribute(scl_tf32_v9, cudaFuncAttributeMaxDynamicSharedMemorySize, SMEM_TOTAL);

    init_flags<<<4, 256>>>();

    // kv fastest-varying: split-K pairs get adjacent block ids -> co-scheduled
    dim3 grid(2, OD / BN, (NQ / BM) * BATCH);   // (2, 8, 128) = 2048 CTAs
    scl_tf32_v9<<<grid, THREADS, SMEM_TOTAL>>>(tx, tw, sid, bias, y);
}

// round 13
// speedup vs baseline: 1.1921x; 1.1921x over previous
#include <cuda_runtime.h>
#include <cuda.h>
#include <cstdint>

// Problem constants
#define BATCH 32
#define NQ    512
#define HD    1024
#define OD    1024
#define NSUBJ 8

// Tiling: CTA 128x128, 4 warps each computing 64x64; K chunk = 32 floats
#define BM 128
#define BN 128
#define BKF 32
#define CHUNKS (HD / BKF)    // 32
#define NST 3
#define THREADS 128

// SMEM layout
#define SMB_FULL(s)  ((s) * 8)
#define SMB_EMPTY(s) (24 + (s) * 8)
#define SM_BIAS      512                 // 128 floats
#define SM_A(s)      (1024 + (s) * 32768)
#define SM_B(s)      (SM_A(s) + 16384)
#define STAGE_BYTES  32768
#define SMEM_TOTAL   (1024 + NST * STAGE_BYTES)   // 99328

__device__ __forceinline__ uint32_t smem_u32(const void* p) {
    return (uint32_t)__cvta_generic_to_shared(p);
}
__device__ __forceinline__ void mbar_init(uint32_t a, uint32_t cnt) {
    asm volatile("mbarrier.init.shared.b64 [%0], %1;" :: "r"(a), "r"(cnt) : "memory");
}
__device__ __forceinline__ void mbar_expect_tx(uint32_t a, uint32_t bytes) {
    asm volatile("mbarrier.arrive.expect_tx.shared.b64 _, [%0], %1;"
                 :: "r"(a), "r"(bytes) : "memory");
}
__device__ __forceinline__ void mbar_arrive(uint32_t a) {
    asm volatile("mbarrier.arrive.shared.b64 _, [%0];" :: "r"(a) : "memory");
}
__device__ __forceinline__ void mbar_wait(uint32_t a, uint32_t parity) {
    asm volatile(
        "{\n\t.reg .pred P;\n"
        "WL%=:\n\tmbarrier.try_wait.parity.shared.b64 P, [%0], %1;\n"
        "\t@P bra WD%=;\n\tbra WL%=;\nWD%=:\n\t}"
        :: "r"(a), "r"(parity) : "memory");
}
__device__ __forceinline__ void tma_load_3d(uint32_t dst, const CUtensorMap* tm,
                                            int cx, int cy, int cz, uint32_t mbar) {
    asm volatile(
        "cp.async.bulk.tensor.3d.shared::cta.global.tile.mbarrier::complete_tx::bytes "
        "[%0], [%1, {%2, %3, %4}], [%5];"
        :: "r"(dst), "l"(tm), "r"(cx), "r"(cy), "r"(cz), "r"(mbar) : "memory");
}
__device__ __forceinline__ uint32_t f2tf32(float f) {
    uint32_t r;
    asm("cvt.rna.tf32.f32 %0, %1;\n" : "=r"(r) : "f"(f));
    return r;
}

// ---------------- main GEMM ----------------
__global__ __launch_bounds__(THREADS, 2)
void scl_tf32_v10(const __grid_constant__ CUtensorMap tma_x,
                  const __grid_constant__ CUtensorMap tma_w,
                  const int*   __restrict__ sid,
                  const float* __restrict__ bias,
                  float*       __restrict__ y) {
    extern __shared__ char smem[];
    const uint32_t sb = smem_u32(smem);

    const int b  = blockIdx.z;
    const int s  = __ldg(&sid[b]);
    const int m0 = blockIdx.y * BM;     // N (query) tile
    const int n0 = blockIdx.x * BN;     // O tile

    const int tid  = threadIdx.x;
    const int wid  = tid >> 5;
    const int lane = tid & 31;
    const int g    = lane >> 2;
    const int tg   = lane & 3;
    const int gx   = g << 2;            // SW128 XOR (word units)
    const int wm   = (wid & 1) * 64;
    const int wn   = (wid >> 1) * 64;

    if (tid == 0) {
        for (int st = 0; st < NST; st++) {
            mbar_init(sb + SMB_FULL(st), 1);
            mbar_init(sb + SMB_EMPTY(st), 4);
        }
    }
    // Prefetch bias tile into smem (one float per thread)
    reinterpret_cast<float*>(smem + SM_BIAS)[tid] = __ldg(&bias[(size_t)s * OD + n0 + tid]);
    __syncthreads();
    if (tid == 0) {
        for (int c = 0; c < NST; c++) {
            mbar_expect_tx(sb + SMB_FULL(c), STAGE_BYTES);
            tma_load_3d(sb + SM_A(c), &tma_x, c * BKF, m0, b, sb + SMB_FULL(c));
            tma_load_3d(sb + SM_B(c), &tma_w, c * BKF, n0, s, sb + SMB_FULL(c));
        }
    }

    float acc[4][8][4];
    #pragma unroll
    for (int i = 0; i < 4; i++)
        #pragma unroll
        for (int j = 0; j < 8; j++)
            #pragma unroll
            for (int k = 0; k < 4; k++) acc[i][j][k] = 0.f;

    uint32_t af0[4][4], bf0[8][2];
    uint32_t af1[4][4], bf1[8][2];

    // A (x): raw fp32 (HW truncates to tf32). B (W): RNA-rounded in-register.
    auto ldfrag = [&](uint32_t af[4][4], uint32_t bf[8][2],
                      const float* A, const float* Bsm, int kl) {
        const int c0k = (kl + tg) ^ gx;
        const int c1k = (kl + tg + 4) ^ gx;
        #pragma unroll
        for (int mi = 0; mi < 4; mi++) {
            const int r0 = wm + mi * 16 + g;
            af[mi][0] = __float_as_uint(A[ r0      * 32 + c0k]);
            af[mi][1] = __float_as_uint(A[(r0 + 8) * 32 + c0k]);
            af[mi][2] = __float_as_uint(A[ r0      * 32 + c1k]);
            af[mi][3] = __float_as_uint(A[(r0 + 8) * 32 + c1k]);
        }
        #pragma unroll
        for (int ni = 0; ni < 8; ni++) {
            const int c0 = wn + ni * 8 + g;
            bf[ni][0] = f2tf32(Bsm[c0 * 32 + c0k]);
            bf[ni][1] = f2tf32(Bsm[c0 * 32 + c1k]);
        }
    };

    auto domma = [&](uint32_t af[4][4], uint32_t bf[8][2]) {
        #pragma unroll
        for (int mi = 0; mi < 4; mi++)
            #pragma unroll
            for (int ni = 0; ni < 8; ni++) {
                asm volatile(
                    "mma.sync.aligned.m16n8k8.row.col.f32.tf32.tf32.f32 "
                    "{%0,%1,%2,%3}, {%4,%5,%6,%7}, {%8,%9}, {%0,%1,%2,%3};\n"
                    : "+f"(acc[mi][ni][0]), "+f"(acc[mi][ni][1]),
                      "+f"(acc[mi][ni][2]), "+f"(acc[mi][ni][3])
                    : "r"(af[mi][0]), "r"(af[mi][1]),
                      "r"(af[mi][2]), "r"(af[mi][3]),
                      "r"(bf[ni][0]), "r"(bf[ni][1]));
            }
    };

    mbar_wait(sb + SMB_FULL(0), 0);
    ldfrag(af0, bf0, (const float*)(smem + SM_A(0)), (const float*)(smem + SM_B(0)), 0);

    int wp = 0;
    for (int kt = 0; kt < CHUNKS; kt++) {
        const int st = kt % NST;
        const float* A   = (const float*)(smem + SM_A(st));
        const float* Bsm = (const float*)(smem + SM_B(st));

        ldfrag(af1, bf1, A, Bsm, 8);
        domma(af0, bf0);
        ldfrag(af0, bf0, A, Bsm, 16);
        domma(af1, bf1);

        // Early wait for next stage — drains behind the queued HMMA work
        const int ns = (kt + 1) % NST;
        if (kt + 1 < CHUNKS) {
            if (ns == 0) wp ^= 1;
            mbar_wait(sb + SMB_FULL(ns), (uint32_t)wp);
        }

        ldfrag(af1, bf1, A, Bsm, 24);
        domma(af0, bf0);

        if (kt + 1 < CHUNKS)
            ldfrag(af0, bf0, (const float*)(smem + SM_A(ns)),
                             (const float*)(smem + SM_B(ns)), 0);
        domma(af1, bf1);

        if (lane == 0) mbar_arrive(sb + SMB_EMPTY(st));

        if (tid == 0 && kt + NST < CHUNKS) {
            mbar_wait(sb + SMB_EMPTY(st), (uint32_t)((kt / NST) & 1));
            mbar_expect_tx(sb + SMB_FULL(st), STAGE_BYTES);
            const int c = kt + NST;
            tma_load_3d(sb + SM_A(st), &tma_x, c * BKF, m0, b, sb + SMB_FULL(st));
            tma_load_3d(sb + SM_B(st), &tma_w, c * BKF, n0, s, sb + SMB_FULL(st));
        }
    }

    // Epilogue: bias (from smem) + store
    const float* bias_s = reinterpret_cast<const float*>(smem + SM_BIAS);
    float* yb = y + (size_t)b * NQ * OD + (size_t)m0 * OD + n0;

    #pragma unroll
    for (int mi = 0; mi < 4; mi++) {
        const int row = wm + mi * 16 + g;
        #pragma unroll
        for (int ni = 0; ni < 8; ni++) {
            const int col = wn + ni * 8 + tg * 2;
            const float b0v = bias_s[col];
            const float b1v = bias_s[col + 1];
            float2 v0 = make_float2(acc[mi][ni][0] + b0v, acc[mi][ni][1] + b1v);
            float2 v1 = make_float2(acc[mi][ni][2] + b0v, acc[mi][ni][3] + b1v);
            *reinterpret_cast<float2*>(&yb[(size_t)row * OD + col])       = v0;
            *reinterpret_cast<float2*>(&yb[(size_t)(row + 8) * OD + col]) = v1;
        }
    }
}

// ---------------- host launch ----------------
typedef int (*PFN_encodeTiled)(
    CUtensorMap*, int, unsigned int, void*,
    const unsigned long long*, const unsigned long long*,
    const unsigned int*, const unsigned int*,
    int, int, int, int);

extern "C" void kernel_launch(void* const* d_in, const int* in_sizes, int n_in,
                              void* d_out, int out_size) {
    const float* x    = (const float*)d_in[0];
    const int*   sid  = (const int*)  d_in[1];
    const float* w    = (const float*)d_in[2];
    const float* bias = (const float*)d_in[3];
    float* y = (float*)d_out;

    PFN_encodeTiled enc = nullptr;
    cudaDriverEntryPointQueryResult qr;
    cudaGetDriverEntryPoint("cuTensorMapEncodeTiled", (void**)&enc, cudaEnableDefault, &qr);

    // Enum ABI values: FLOAT32=7, interleave NONE=0, SWIZZLE_128B=3, L2_128B=2, OOB NONE=0
    CUtensorMap tx{}, tw{};
    {
        unsigned long long dims[3]    = {HD, NQ, BATCH};
        unsigned long long strides[2] = {HD * 4ull, (unsigned long long)NQ * HD * 4ull};
        unsigned int box[3]           = {BKF, BM, 1};
        unsigned int es[3]            = {1, 1, 1};
        enc(&tx, 7, 3, (void*)x, dims, strides, box, es, 0, 3, 2, 0);
    }
    {
        unsigned long long dims[3]    = {HD, OD, NSUBJ};
        unsigned long long strides[2] = {HD * 4ull, (unsigned long long)OD * HD * 4ull};
        unsigned int box[3]           = {BKF, BN, 1};
        unsigned int es[3]            = {1, 1, 1};
        enc(&tw, 7, 3, (void*)w, dims, strides, box, es, 0, 3, 2, 0);
    }

    cudaFuncSetAttribute(scl_tf32_v10, cudaFuncAttributeMaxDynamicSharedMemorySize, SMEM_TOTAL);

    dim3 grid(OD / BN, NQ / BM, BATCH);  // (8, 4, 32) = 1024 CTAs
    scl_tf32_v10<<<grid, THREADS, SMEM_TOTAL>>>(tx, tw, sid, bias, y);
}

// round 14
// speedup vs baseline: 1.2276x; 1.0298x over previous
#include <cuda_runtime.h>
#include <cuda.h>
#include <cstdint>

// Problem constants
#define BATCH 32
#define NQ    512
#define HD    1024
#define OD    1024
#define NSUBJ 8

// Tiling: CTA 128x128, 4 warps each computing 64x64; K chunk = 32 floats
#define BM 128
#define BN 128
#define BKF 32
#define CHUNKS 32
#define NST 3
#define THREADS 128

// Work decomposition: 1024 output tiles. First 888 (= 3 full waves of 296
// CTA-slots) are full-K CTAs. The 136 leftover tiles are split-K x2 into 272
// half-CTAs forming a short tail wave.
#define NFULL  888
#define NPAIRS 136
#define NGRID  (NFULL + 2 * NPAIRS)   // 1160

// SMEM layout
#define SMB_FULL(s)  ((s) * 8)
#define SMB_EMPTY(s) (24 + (s) * 8)
#define SM_A(s)      (1024 + (s) * 32768)
#define SM_B(s)      (SM_A(s) + 16384)
#define STAGE_BYTES  32768
#define SMEM_TOTAL   (1024 + NST * STAGE_BYTES)   // 99328

// Split-K scratch (tail tiles only): 136 * 64KB = 8.9MB (L2-resident) + flags
__device__ float g_part[(size_t)NPAIRS * BM * BN];
__device__ int   g_flag[NPAIRS];

__device__ __forceinline__ uint32_t smem_u32(const void* p) {
    return (uint32_t)__cvta_generic_to_shared(p);
}
__device__ __forceinline__ void mbar_init(uint32_t a, uint32_t cnt) {
    asm volatile("mbarrier.init.shared.b64 [%0], %1;" :: "r"(a), "r"(cnt) : "memory");
}
__device__ __forceinline__ void mbar_expect_tx(uint32_t a, uint32_t bytes) {
    asm volatile("mbarrier.arrive.expect_tx.shared.b64 _, [%0], %1;"
                 :: "r"(a), "r"(bytes) : "memory");
}
__device__ __forceinline__ void mbar_arrive(uint32_t a) {
    asm volatile("mbarrier.arrive.shared.b64 _, [%0];" :: "r"(a) : "memory");
}
__device__ __forceinline__ void mbar_wait(uint32_t a, uint32_t parity) {
    asm volatile(
        "{\n\t.reg .pred P;\n"
        "WL%=:\n\tmbarrier.try_wait.parity.shared.b64 P, [%0], %1;\n"
        "\t@P bra WD%=;\n\tbra WL%=;\nWD%=:\n\t}"
        :: "r"(a), "r"(parity) : "memory");
}
__device__ __forceinline__ void tma_load_3d(uint32_t dst, const CUtensorMap* tm,
                                            int cx, int cy, int cz, uint32_t mbar) {
    asm volatile(
        "cp.async.bulk.tensor.3d.shared::cta.global.tile.mbarrier::complete_tx::bytes "
        "[%0], [%1, {%2, %3, %4}], [%5];"
        :: "r"(dst), "l"(tm), "r"(cx), "r"(cy), "r"(cz), "r"(mbar) : "memory");
}

// ---------------- flag init (graph-replay safe) ----------------
__global__ void __launch_bounds__(256) init_flags() {
    const int i = blockIdx.x * blockDim.x + threadIdx.x;
    if (i < NPAIRS) g_flag[i] = 0;
}

// ---------------- main GEMM ----------------
__global__ __launch_bounds__(THREADS, 2)
void scl_tf32_v11(const __grid_constant__ CUtensorMap tma_x,
                  const __grid_constant__ CUtensorMap tma_w,
                  const int*   __restrict__ sid,
                  const float* __restrict__ bias,
                  float*       __restrict__ y) {
    extern __shared__ char smem[];
    const uint32_t sb = smem_u32(smem);

    // Decode work unit
    const int bid = blockIdx.x;
    int t, kv = -1, pair = 0;
    if (bid < NFULL) {
        t = bid;
    } else {
        const int i = bid - NFULL;
        pair = i >> 1;
        kv   = i & 1;
        t = NFULL + pair;
    }
    const int n0 = (t & 7) * BN;
    const int m0 = ((t >> 3) & 3) * BM;
    const int b  = t >> 5;
    const int s  = __ldg(&sid[b]);
    const int cbase = (kv == 1) ? (CHUNKS / 2) : 0;
    const int nch   = (kv < 0) ? CHUNKS : (CHUNKS / 2);

    const int tid  = threadIdx.x;
    const int wid  = tid >> 5;
    const int lane = tid & 31;
    const int g    = lane >> 2;
    const int tg   = lane & 3;
    const int gx   = g << 2;            // SW128 XOR (word units)
    const int wm   = (wid & 1) * 64;
    const int wn   = (wid >> 1) * 64;

    if (tid == 0) {
        for (int st = 0; st < NST; st++) {
            mbar_init(sb + SMB_FULL(st), 1);
            mbar_init(sb + SMB_EMPTY(st), 4);
        }
    }
    __syncthreads();
    if (tid == 0) {
        for (int c = 0; c < NST; c++) {
            mbar_expect_tx(sb + SMB_FULL(c), STAGE_BYTES);
            tma_load_3d(sb + SM_A(c), &tma_x, (cbase + c) * BKF, m0, b, sb + SMB_FULL(c));
            tma_load_3d(sb + SM_B(c), &tma_w, (cbase + c) * BKF, n0, s, sb + SMB_FULL(c));
        }
    }

    float acc[4][8][4];
    #pragma unroll
    for (int i = 0; i < 4; i++)
        #pragma unroll
        for (int j = 0; j < 8; j++)
            #pragma unroll
            for (int k = 0; k < 4; k++) acc[i][j][k] = 0.f;

    uint32_t af0[4][4], bf0[8][2];
    uint32_t af1[4][4], bf1[8][2];

    // A (x): raw fp32 — HW truncates to tf32.
    // B (W): +0x1000 on the bit pattern = round-half-away of the 13 truncated
    //        bits = bit-exact cvt.rna.tf32, at IADD cost instead of CVT.
    auto ldfrag = [&](uint32_t af[4][4], uint32_t bf[8][2],
                      const float* A, const float* Bsm, int kl) {
        const int c0k = (kl + tg) ^ gx;
        const int c1k = (kl + tg + 4) ^ gx;
        #pragma unroll
        for (int mi = 0; mi < 4; mi++) {
            const int r0 = wm + mi * 16 + g;
            af[mi][0] = __float_as_uint(A[ r0      * 32 + c0k]);
            af[mi][1] = __float_as_uint(A[(r0 + 8) * 32 + c0k]);
            af[mi][2] = __float_as_uint(A[ r0      * 32 + c1k]);
            af[mi][3] = __float_as_uint(A[(r0 + 8) * 32 + c1k]);
        }
        #pragma unroll
        for (int ni = 0; ni < 8; ni++) {
            const int c0 = wn + ni * 8 + g;
            bf[ni][0] = __float_as_uint(Bsm[c0 * 32 + c0k]) + 0x1000u;
            bf[ni][1] = __float_as_uint(Bsm[c0 * 32 + c1k]) + 0x1000u;
        }
    };

    auto domma = [&](uint32_t af[4][4], uint32_t bf[8][2]) {
        #pragma unroll
        for (int mi = 0; mi < 4; mi++)
            #pragma unroll
            for (int ni = 0; ni < 8; ni++) {
                asm volatile(
                    "mma.sync.aligned.m16n8k8.row.col.f32.tf32.tf32.f32 "
                    "{%0,%1,%2,%3}, {%4,%5,%6,%7}, {%8,%9}, {%0,%1,%2,%3};\n"
                    : "+f"(acc[mi][ni][0]), "+f"(acc[mi][ni][1]),
                      "+f"(acc[mi][ni][2]), "+f"(acc[mi][ni][3])
                    : "r"(af[mi][0]), "r"(af[mi][1]),
                      "r"(af[mi][2]), "r"(af[mi][3]),
                      "r"(bf[ni][0]), "r"(bf[ni][1]));
            }
    };

    mbar_wait(sb + SMB_FULL(0), 0);
    ldfrag(af0, bf0, (const float*)(smem + SM_A(0)), (const float*)(smem + SM_B(0)), 0);

    int wp = 0;
    for (int kt = 0; kt < nch; kt++) {
        const int st = kt % NST;
        const float* A   = (const float*)(smem + SM_A(st));
        const float* Bsm = (const float*)(smem + SM_B(st));

        ldfrag(af1, bf1, A, Bsm, 8);
        domma(af0, bf0);
        ldfrag(af0, bf0, A, Bsm, 16);
        domma(af1, bf1);
        ldfrag(af1, bf1, A, Bsm, 24);
        domma(af0, bf0);

        if (kt + 1 < nch) {
            const int ns = (kt + 1) % NST;
            if (ns == 0) wp ^= 1;
            mbar_wait(sb + SMB_FULL(ns), (uint32_t)wp);
            ldfrag(af0, bf0, (const float*)(smem + SM_A(ns)),
                             (const float*)(smem + SM_B(ns)), 0);
        }
        domma(af1, bf1);

        if (lane == 0) mbar_arrive(sb + SMB_EMPTY(st));

        if (tid == 0 && kt + NST < nch) {
            mbar_wait(sb + SMB_EMPTY(st), (uint32_t)((kt / NST) & 1));
            mbar_expect_tx(sb + SMB_FULL(st), STAGE_BYTES);
            const int c = cbase + kt + NST;
            tma_load_3d(sb + SM_A(st), &tma_x, c * BKF, m0, b, sb + SMB_FULL(st));
            tma_load_3d(sb + SM_B(st), &tma_w, c * BKF, n0, s, sb + SMB_FULL(st));
        }
    }

    // ---- Epilogues ----
    if (kv == 0) {
        // Tail producer: write partial, release flag.
        float* pp = g_part + (size_t)pair * (BM * BN);
        #pragma unroll
        for (int mi = 0; mi < 4; mi++) {
            const int row = wm + mi * 16 + g;
            #pragma unroll
            for (int ni = 0; ni < 8; ni++) {
                const int col = wn + ni * 8 + tg * 2;
                *reinterpret_cast<float2*>(&pp[row * BN + col]) =
                    make_float2(acc[mi][ni][0], acc[mi][ni][1]);
                *reinterpret_cast<float2*>(&pp[(row + 8) * BN + col]) =
                    make_float2(acc[mi][ni][2], acc[mi][ni][3]);
            }
        }
        __threadfence();
        __syncthreads();
        if (tid == 0) {
            asm volatile("st.release.gpu.global.b32 [%0], %1;"
                         :: "l"(&g_flag[pair]), "r"(1) : "memory");
        }
        return;
    }

    if (kv == 1) {
        if (tid == 0) {
            int v = 0;
            do {
                asm volatile("ld.acquire.gpu.global.b32 %0, [%1];"
                             : "=r"(v) : "l"(&g_flag[pair]) : "memory");
                if (!v) __nanosleep(128);
            } while (!v);
        }
        __syncthreads();
        const float* pp = g_part + (size_t)pair * (BM * BN);
        const float* bb = bias + (size_t)s * OD + n0;
        float* yb = y + (size_t)b * NQ * OD + (size_t)m0 * OD + n0;
        #pragma unroll
        for (int mi = 0; mi < 4; mi++) {
            const int row = wm + mi * 16 + g;
            #pragma unroll
            for (int ni = 0; ni < 8; ni++) {
                const int col = wn + ni * 8 + tg * 2;
                const float b0v = __ldg(&bb[col]);
                const float b1v = __ldg(&bb[col + 1]);
                const float2 p0 = *reinterpret_cast<const float2*>(&pp[row * BN + col]);
                const float2 p1 = *reinterpret_cast<const float2*>(&pp[(row + 8) * BN + col]);
                float2 v0 = make_float2((p0.x + acc[mi][ni][0]) + b0v,
                                        (p0.y + acc[mi][ni][1]) + b1v);
                float2 v1 = make_float2((p1.x + acc[mi][ni][2]) + b0v,
                                        (p1.y + acc[mi][ni][3]) + b1v);
                *reinterpret_cast<float2*>(&yb[(size_t)row * OD + col])       = v0;
                *reinterpret_cast<float2*>(&yb[(size_t)(row + 8) * OD + col]) = v1;
            }
        }
        return;
    }

    // Full-tile epilogue: bias + store (R8 form)
    const float* bb = bias + (size_t)s * OD + n0;
    float* yb = y + (size_t)b * NQ * OD + (size_t)m0 * OD + n0;
    #pragma unroll
    for (int mi = 0; mi < 4; mi++) {
        const int row = wm + mi * 16 + g;
        #pragma unroll
        for (int ni = 0; ni < 8; ni++) {
            const int col = wn + ni * 8 + tg * 2;
            const float b0v = __ldg(&bb[col]);
            const float b1v = __ldg(&bb[col + 1]);
            float2 v0 = make_float2(acc[mi][ni][0] + b0v, acc[mi][ni][1] + b1v);
            float2 v1 = make_float2(acc[mi][ni][2] + b0v, acc[mi][ni][3] + b1v);
            *reinterpret_cast<float2*>(&yb[(size_t)row * OD + col])       = v0;
            *reinterpret_cast<float2*>(&yb[(size_t)(row + 8) * OD + col]) = v1;
        }
    }
}

// ---------------- host launch ----------------
typedef int (*PFN_encodeTiled)(
    CUtensorMap*, int, unsigned int, void*,
    const unsigned long long*, const unsigned long long*,
    const unsigned int*, const unsigned int*,
    int, int, int, int);

extern "C" void kernel_launch(void* const* d_in, const int* in_sizes, int n_in,
                              void* d_out, int out_size) {
    const float* x    = (const float*)d_in[0];
    const int*   sid  = (const int*)  d_in[1];
    const float* w    = (const float*)d_in[2];
    const float* bias = (const float*)d_in[3];
    float* y = (float*)d_out;

    PFN_encodeTiled enc = nullptr;
    cudaDriverEntryPointQueryResult qr;
    cudaGetDriverEntryPoint("cuTensorMapEncodeTiled", (void**)&enc, cudaEnableDefault, &qr);

    // Enum ABI values: FLOAT32=7, interleave NONE=0, SWIZZLE_128B=3, L2_128B=2, OOB NONE=0
    CUtensorMap tx{}, tw{};
    {
        unsigned long long dims[3]    = {HD, NQ, BATCH};
        unsigned long long strides[2] = {HD * 4ull, (unsigned long long)NQ * HD * 4ull};
        unsigned int box[3]           = {BKF, BM, 1};
        unsigned int es[3]            = {1, 1, 1};
        enc(&tx, 7, 3, (void*)x, dims, strides, box, es, 0, 3, 2, 0);
    }
    {
        unsigned long long dims[3]    = {HD, OD, NSUBJ};
        unsigned long long strides[2] = {HD * 4ull, (unsigned long long)OD * HD * 4ull};
        unsigned int box[3]           = {BKF, BN, 1};
        unsigned int es[3]            = {1, 1, 1};
        enc(&tw, 7, 3, (void*)w, dims, strides, box, es, 0, 3, 2, 0);
    }

    cudaFuncSetAttribute(scl_tf32_v11, cudaFuncAttributeMaxDynamicSharedMemorySize, SMEM_TOTAL);

    init_flags<<<1, 256>>>();
    scl_tf32_v11<<<NGRID, THREADS, SMEM_TOTAL>>>(tx, tw, sid, bias, y);
}

// round 15
// speedup vs baseline: 1.2468x; 1.0156x over previous
#include <cuda_runtime.h>
#include <cuda.h>
#include <cstdint>

// Problem constants
#define BATCH 32
#define NQ    512
#define HD    1024
#define OD    1024
#define NSUBJ 8

// Tiling: CTA 128x128, 4 warps each computing 64x64; K chunk = 32 floats
#define BM 128
#define BN 128
#define BKF 32
#define CHUNKS (HD / BKF)    // 32
#define NST 3
#define THREADS 128

// SMEM layout
#define SMB_FULL(s)  ((s) * 8)
#define SMB_EMPTY(s) (24 + (s) * 8)
#define SM_A(s)      (1024 + (s) * 32768)
#define SM_B(s)      (SM_A(s) + 16384)
#define STAGE_BYTES  32768
#define SMEM_TOTAL   (1024 + NST * STAGE_BYTES)   // 99328

__device__ __forceinline__ uint32_t smem_u32(const void* p) {
    return (uint32_t)__cvta_generic_to_shared(p);
}
__device__ __forceinline__ void mbar_init(uint32_t a, uint32_t cnt) {
    asm volatile("mbarrier.init.shared.b64 [%0], %1;" :: "r"(a), "r"(cnt) : "memory");
}
__device__ __forceinline__ void mbar_expect_tx(uint32_t a, uint32_t bytes) {
    asm volatile("mbarrier.arrive.expect_tx.shared.b64 _, [%0], %1;"
                 :: "r"(a), "r"(bytes) : "memory");
}
__device__ __forceinline__ void mbar_arrive(uint32_t a) {
    asm volatile("mbarrier.arrive.shared.b64 _, [%0];" :: "r"(a) : "memory");
}
__device__ __forceinline__ void mbar_wait(uint32_t a, uint32_t parity) {
    asm volatile(
        "{\n\t.reg .pred P;\n"
        "WL%=:\n\tmbarrier.try_wait.parity.shared.b64 P, [%0], %1;\n"
        "\t@P bra WD%=;\n\tbra WL%=;\nWD%=:\n\t}"
        :: "r"(a), "r"(parity) : "memory");
}
__device__ __forceinline__ void tma_load_3d(uint32_t dst, const CUtensorMap* tm,
                                            int cx, int cy, int cz, uint32_t mbar) {
    asm volatile(
        "cp.async.bulk.tensor.3d.shared::cta.global.tile.mbarrier::complete_tx::bytes "
        "[%0], [%1, {%2, %3, %4}], [%5];"
        :: "r"(dst), "l"(tm), "r"(cx), "r"(cy), "r"(cz), "r"(mbar) : "memory");
}

// ---------------- main GEMM ----------------
__global__ __launch_bounds__(THREADS, 2)
void scl_tf32_v12(const __grid_constant__ CUtensorMap tma_x,
                  const __grid_constant__ CUtensorMap tma_w,
                  const int*   __restrict__ sid,
                  const float* __restrict__ bias,
                  float*       __restrict__ y) {
    extern __shared__ char smem[];
    const uint32_t sb = smem_u32(smem);

    const int b  = blockIdx.z;
    const int s  = __ldg(&sid[b]);
    const int m0 = blockIdx.y * BM;     // N (query) tile
    const int n0 = blockIdx.x * BN;     // O tile

    const int tid  = threadIdx.x;
    const int wid  = tid >> 5;
    const int lane = tid & 31;
    const int g    = lane >> 2;
    const int tg   = lane & 3;
    const int gx   = g << 2;            // SW128 XOR (word units)
    const int wm   = (wid & 1) * 64;
    const int wn   = (wid >> 1) * 64;

    if (tid == 0) {
        for (int st = 0; st < NST; st++) {
            mbar_init(sb + SMB_FULL(st), 1);
            mbar_init(sb + SMB_EMPTY(st), 4);
        }
    }
    __syncthreads();
    if (tid == 0) {
        for (int c = 0; c < NST; c++) {
            mbar_expect_tx(sb + SMB_FULL(c), STAGE_BYTES);
            tma_load_3d(sb + SM_A(c), &tma_x, c * BKF, m0, b, sb + SMB_FULL(c));
            tma_load_3d(sb + SM_B(c), &tma_w, c * BKF, n0, s, sb + SMB_FULL(c));
        }
    }

    float acc[4][8][4];
    #pragma unroll
    for (int i = 0; i < 4; i++)
        #pragma unroll
        for (int j = 0; j < 8; j++)
            #pragma unroll
            for (int k = 0; k < 4; k++) acc[i][j][k] = 0.f;

    uint32_t af0[4][4], bf0[8][2];
    uint32_t af1[4][4], bf1[8][2];

    // A (x): raw fp32 — HW truncates to tf32.
    // B (W): +0x1000 on the bit pattern = round-half-away of the 13 truncated
    //        bits = bit-exact cvt.rna.tf32 at IADD cost (validated R14).
    auto ldfrag = [&](uint32_t af[4][4], uint32_t bf[8][2],
                      const float* A, const float* Bsm, int kl) {
        const int c0k = (kl + tg) ^ gx;
        const int c1k = (kl + tg + 4) ^ gx;
        #pragma unroll
        for (int mi = 0; mi < 4; mi++) {
            const int r0 = wm + mi * 16 + g;
            af[mi][0] = __float_as_uint(A[ r0      * 32 + c0k]);
            af[mi][1] = __float_as_uint(A[(r0 + 8) * 32 + c0k]);
            af[mi][2] = __float_as_uint(A[ r0      * 32 + c1k]);
            af[mi][3] = __float_as_uint(A[(r0 + 8) * 32 + c1k]);
        }
        #pragma unroll
        for (int ni = 0; ni < 8; ni++) {
            const int c0 = wn + ni * 8 + g;
            bf[ni][0] = __float_as_uint(Bsm[c0 * 32 + c0k]) + 0x1000u;
            bf[ni][1] = __float_as_uint(Bsm[c0 * 32 + c1k]) + 0x1000u;
        }
    };

    auto domma = [&](uint32_t af[4][4], uint32_t bf[8][2]) {
        #pragma unroll
        for (int mi = 0; mi < 4; mi++)
            #pragma unroll
            for (int ni = 0; ni < 8; ni++) {
                asm volatile(
                    "mma.sync.aligned.m16n8k8.row.col.f32.tf32.tf32.f32 "
                    "{%0,%1,%2,%3}, {%4,%5,%6,%7}, {%8,%9}, {%0,%1,%2,%3};\n"
                    : "+f"(acc[mi][ni][0]), "+f"(acc[mi][ni][1]),
                      "+f"(acc[mi][ni][2]), "+f"(acc[mi][ni][3])
                    : "r"(af[mi][0]), "r"(af[mi][1]),
                      "r"(af[mi][2]), "r"(af[mi][3]),
                      "r"(bf[ni][0]), "r"(bf[ni][1]));
            }
    };

    mbar_wait(sb + SMB_FULL(0), 0);
    ldfrag(af0, bf0, (const float*)(smem + SM_A(0)), (const float*)(smem + SM_B(0)), 0);

    int wp = 0;
    for (int kt = 0; kt < CHUNKS; kt++) {
        const int st = kt % NST;
        const float* A   = (const float*)(smem + SM_A(st));
        const float* Bsm = (const float*)(smem + SM_B(st));

        ldfrag(af1, bf1, A, Bsm, 8);
        domma(af0, bf0);
        ldfrag(af0, bf0, A, Bsm, 16);
        domma(af1, bf1);
        ldfrag(af1, bf1, A, Bsm, 24);

        // Stage st fully consumed into registers — signal empty NOW
        // (two domma blocks earlier than before: more producer lead).
        if (lane == 0) mbar_arrive(sb + SMB_EMPTY(st));

        domma(af0, bf0);

        if (kt + 1 < CHUNKS) {
            const int ns = (kt + 1) % NST;
            if (ns == 0) wp ^= 1;
            mbar_wait(sb + SMB_FULL(ns), (uint32_t)wp);
            ldfrag(af0, bf0, (const float*)(smem + SM_A(ns)),
                             (const float*)(smem + SM_B(ns)), 0);
        }
        domma(af1, bf1);

        if (tid == 0 && kt + NST < CHUNKS) {
            mbar_wait(sb + SMB_EMPTY(st), (uint32_t)((kt / NST) & 1));
            mbar_expect_tx(sb + SMB_FULL(st), STAGE_BYTES);
            const int c = kt + NST;
            tma_load_3d(sb + SM_A(st), &tma_x, c * BKF, m0, b, sb + SMB_FULL(st));
            tma_load_3d(sb + SM_B(st), &tma_w, c * BKF, n0, s, sb + SMB_FULL(st));
        }
    }

    // Epilogue: bias add + store
    const float* bb = bias + (size_t)s * OD + n0;
    float* yb = y + (size_t)b * NQ * OD + (size_t)m0 * OD + n0;

    #pragma unroll
    for (int mi = 0; mi < 4; mi++) {
        const int row = wm + mi * 16 + g;
        #pragma unroll
        for (int ni = 0; ni < 8; ni++) {
            const int col = wn + ni * 8 + tg * 2;
            const float b0v = __ldg(&bb[col]);
            const float b1v = __ldg(&bb[col + 1]);
            float2 v0 = make_float2(acc[mi][ni][0] + b0v, acc[mi][ni][1] + b1v);
            float2 v1 = make_float2(acc[mi][ni][2] + b0v, acc[mi][ni][3] + b1v);
            *reinterpret_cast<float2*>(&yb[(size_t)row * OD + col])       = v0;
            *reinterpret_cast<float2*>(&yb[(size_t)(row + 8) * OD + col]) = v1;
        }
    }
}

// ---------------- host launch ----------------
typedef int (*PFN_encodeTiled)(
    CUtensorMap*, int, unsigned int, void*,
    const unsigned long long*, const unsigned long long*,
    const unsigned int*, const unsigned int*,
    int, int, int, int);

extern "C" void kernel_launch(void* const* d_in, const int* in_sizes, int n_in,
                              void* d_out, int out_size) {
    const float* x    = (const float*)d_in[0];
    const int*   sid  = (const int*)  d_in[1];
    const float* w    = (const float*)d_in[2];
    const float* bias = (const float*)d_in[3];
    float* y = (float*)d_out;

    PFN_encodeTiled enc = nullptr;
    cudaDriverEntryPointQueryResult qr;
    cudaGetDriverEntryPoint("cuTensorMapEncodeTiled", (void**)&enc, cudaEnableDefault, &qr);

    // Enum ABI values: FLOAT32=7, interleave NONE=0, SWIZZLE_128B=3, L2_128B=2, OOB NONE=0
    CUtensorMap tx{}, tw{};
    {
        unsigned long long dims[3]    = {HD, NQ, BATCH};
        unsigned long long strides[2] = {HD * 4ull, (unsigned long long)NQ * HD * 4ull};
        unsigned int box[3]           = {BKF, BM, 1};
        unsigned int es[3]            = {1, 1, 1};
        enc(&tx, 7, 3, (void*)x, dims, strides, box, es, 0, 3, 2, 0);
    }
    {
        unsigned long long dims[3]    = {HD, OD, NSUBJ};
        unsigned long long strides[2] = {HD * 4ull, (unsigned long long)OD * HD * 4ull};
        unsigned int box[3]           = {BKF, BN, 1};
        unsigned int es[3]            = {1, 1, 1};
        enc(&tw, 7, 3, (void*)w, dims, strides, box, es, 0, 3, 2, 0);
    }

    cudaFuncSetAttribute(scl_tf32_v12, cudaFuncAttributeMaxDynamicSharedMemorySize, SMEM_TOTAL);

    dim3 grid(OD / BN, NQ / BM, BATCH);  // (8, 4, 32) = 1024 CTAs
    scl_tf32_v12<<<grid, THREADS, SMEM_TOTAL>>>(tx, tw, sid, bias, y);
}

// round 16
// speedup vs baseline: 1.2940x; 1.0379x over previous
#include <cuda_runtime.h>
#include <cuda.h>
#include <cstdint>

// Problem constants
#define BATCH 32
#define NQ    512
#define HD    1024
#define OD    1024
#define NSUBJ 8

// Tiling: CTA 128x128, 4 warps each computing 64x64; K chunk = 32 floats
#define BM 128
#define BN 128
#define BKF 32
#define CHUNKS (HD / BKF)    // 32 per tile
#define NST 3
#define THREADS 128
#define NCTA 296             // persistent: 2 per SM, full wave-1 residency
#define NTILES 1024

// SMEM layout
#define SMB_FULL(s)  ((s) * 8)
#define SMB_EMPTY(s) (24 + (s) * 8)
#define SM_A(s)      (1024 + (s) * 32768)
#define SM_B(s)      (SM_A(s) + 16384)
#define STAGE_BYTES  32768
#define SMEM_TOTAL   (1024 + NST * STAGE_BYTES)   // 99328

__device__ __forceinline__ uint32_t smem_u32(const void* p) {
    return (uint32_t)__cvta_generic_to_shared(p);
}
__device__ __forceinline__ void mbar_init(uint32_t a, uint32_t cnt) {
    asm volatile("mbarrier.init.shared.b64 [%0], %1;" :: "r"(a), "r"(cnt) : "memory");
}
__device__ __forceinline__ void mbar_expect_tx(uint32_t a, uint32_t bytes) {
    asm volatile("mbarrier.arrive.expect_tx.shared.b64 _, [%0], %1;"
                 :: "r"(a), "r"(bytes) : "memory");
}
__device__ __forceinline__ void mbar_arrive(uint32_t a) {
    asm volatile("mbarrier.arrive.shared.b64 _, [%0];" :: "r"(a) : "memory");
}
__device__ __forceinline__ void mbar_wait(uint32_t a, uint32_t parity) {
    asm volatile(
        "{\n\t.reg .pred P;\n"
        "WL%=:\n\tmbarrier.try_wait.parity.shared.b64 P, [%0], %1;\n"
        "\t@P bra WD%=;\n\tbra WL%=;\nWD%=:\n\t}"
        :: "r"(a), "r"(parity) : "memory");
}
__device__ __forceinline__ void tma_load_3d(uint32_t dst, const CUtensorMap* tm,
                                            int cx, int cy, int cz, uint32_t mbar) {
    asm volatile(
        "cp.async.bulk.tensor.3d.shared::cta.global.tile.mbarrier::complete_tx::bytes "
        "[%0], [%1, {%2, %3, %4}], [%5];"
        :: "r"(dst), "l"(tm), "r"(cx), "r"(cy), "r"(cz), "r"(mbar) : "memory");
}

// ---------------- main GEMM: persistent CTAs, continuous pipeline ----------
__global__ __launch_bounds__(THREADS, 2)
void scl_tf32_v13(const __grid_constant__ CUtensorMap tma_x,
                  const __grid_constant__ CUtensorMap tma_w,
                  const int*   __restrict__ sid,
                  const float* __restrict__ bias,
                  float*       __restrict__ y) {
    extern __shared__ char smem[];
    const uint32_t sb = smem_u32(smem);

    const int cta    = blockIdx.x;                       // 0..295
    const int ntiles = (cta < NTILES - 3 * NCTA) ? 4 : 3;  // 136 do 4, 160 do 3
    const int total  = ntiles * CHUNKS;

    const int tid  = threadIdx.x;
    const int wid  = tid >> 5;
    const int lane = tid & 31;
    const int g    = lane >> 2;
    const int tg   = lane & 3;
    const int gx   = g << 2;            // SW128 XOR (word units)
    const int wm   = (wid & 1) * 64;
    const int wn   = (wid >> 1) * 64;

    if (tid == 0) {
        for (int st = 0; st < NST; st++) {
            mbar_init(sb + SMB_FULL(st), 1);
            mbar_init(sb + SMB_EMPTY(st), 4);
        }
    }
    __syncthreads();
    if (tid == 0) {
        // First NST chunks all belong to tile 0 of this CTA (CHUNKS=32 > NST)
        const int t0 = cta;
        const int n0i = (t0 & 7) * BN;
        const int m0i = ((t0 >> 3) & 3) * BM;
        const int bi  = t0 >> 5;
        const int si  = __ldg(&sid[bi]);
        for (int c = 0; c < NST; c++) {
            mbar_expect_tx(sb + SMB_FULL(c), STAGE_BYTES);
            tma_load_3d(sb + SM_A(c), &tma_x, c * BKF, m0i, bi, sb + SMB_FULL(c));
            tma_load_3d(sb + SM_B(c), &tma_w, c * BKF, n0i, si, sb + SMB_FULL(c));
        }
    }

    float acc[4][8][4];
    #pragma unroll
    for (int i = 0; i < 4; i++)
        #pragma unroll
        for (int j = 0; j < 8; j++)
            #pragma unroll
            for (int k = 0; k < 4; k++) acc[i][j][k] = 0.f;

    uint32_t af0[4][4], bf0[8][2];
    uint32_t af1[4][4], bf1[8][2];

    // A (x): raw fp32 — HW truncates to tf32.
    // B (W): +0x1000 = bit-exact cvt.rna.tf32 at IADD cost (validated R14/15).
    auto ldfrag = [&](uint32_t af[4][4], uint32_t bf[8][2],
                      const float* A, const float* Bsm, int kl) {
        const int c0k = (kl + tg) ^ gx;
        const int c1k = (kl + tg + 4) ^ gx;
        #pragma unroll
        for (int mi = 0; mi < 4; mi++) {
            const int r0 = wm + mi * 16 + g;
            af[mi][0] = __float_as_uint(A[ r0      * 32 + c0k]);
            af[mi][1] = __float_as_uint(A[(r0 + 8) * 32 + c0k]);
            af[mi][2] = __float_as_uint(A[ r0      * 32 + c1k]);
            af[mi][3] = __float_as_uint(A[(r0 + 8) * 32 + c1k]);
        }
        #pragma unroll
        for (int ni = 0; ni < 8; ni++) {
            const int c0 = wn + ni * 8 + g;
            bf[ni][0] = __float_as_uint(Bsm[c0 * 32 + c0k]) + 0x1000u;
            bf[ni][1] = __float_as_uint(Bsm[c0 * 32 + c1k]) + 0x1000u;
        }
    };

    auto domma = [&](uint32_t af[4][4], uint32_t bf[8][2]) {
        #pragma unroll
        for (int mi = 0; mi < 4; mi++)
            #pragma unroll
            for (int ni = 0; ni < 8; ni++) {
                asm volatile(
                    "mma.sync.aligned.m16n8k8.row.col.f32.tf32.tf32.f32 "
                    "{%0,%1,%2,%3}, {%4,%5,%6,%7}, {%8,%9}, {%0,%1,%2,%3};\n"
                    : "+f"(acc[mi][ni][0]), "+f"(acc[mi][ni][1]),
                      "+f"(acc[mi][ni][2]), "+f"(acc[mi][ni][3])
                    : "r"(af[mi][0]), "r"(af[mi][1]),
                      "r"(af[mi][2]), "r"(af[mi][3]),
                      "r"(bf[ni][0]), "r"(bf[ni][1]));
            }
    };

    // Wait chunk 0, preload its ks=0 fragments
    mbar_wait(sb + SMB_FULL(0), 0);
    ldfrag(af0, bf0, (const float*)(smem + SM_A(0)), (const float*)(smem + SM_B(0)), 0);

    for (int ti = 0; ti < ntiles; ti++) {
        const int t  = cta + ti * NCTA;
        const int n0 = (t & 7) * BN;
        const int m0 = ((t >> 3) & 3) * BM;
        const int b  = t >> 5;
        const int s  = __ldg(&sid[b]);

        for (int kt = 0; kt < CHUNKS; kt++) {
            const int gc = ti * CHUNKS + kt;
            const int st = gc % NST;
            const float* A   = (const float*)(smem + SM_A(st));
            const float* Bsm = (const float*)(smem + SM_B(st));

            ldfrag(af1, bf1, A, Bsm, 8);
            domma(af0, bf0);
            ldfrag(af0, bf0, A, Bsm, 16);
            domma(af1, bf1);
            ldfrag(af1, bf1, A, Bsm, 24);

            // Stage st fully consumed into registers — signal empty now
            if (lane == 0) mbar_arrive(sb + SMB_EMPTY(st));

            domma(af0, bf0);

            if (gc + 1 < total) {
                const int ns = (gc + 1) % NST;
                mbar_wait(sb + SMB_FULL(ns), (uint32_t)(((gc + 1) / NST) & 1));
                ldfrag(af0, bf0, (const float*)(smem + SM_A(ns)),
                                 (const float*)(smem + SM_B(ns)), 0);
            }
            domma(af1, bf1);

            // Producer: refill this slot with global chunk gc+NST (possibly
            // belonging to the NEXT tile -> epilogue overlaps these loads)
            if (tid == 0 && gc + NST < total) {
                const int c2 = gc + NST;
                mbar_wait(sb + SMB_EMPTY(st), (uint32_t)((gc / NST) & 1));
                mbar_expect_tx(sb + SMB_FULL(st), STAGE_BYTES);
                const int t2  = cta + (c2 >> 5) * NCTA;
                const int kk  = c2 & 31;
                const int n02 = (t2 & 7) * BN;
                const int m02 = ((t2 >> 3) & 3) * BM;
                const int b2  = t2 >> 5;
                const int s2  = __ldg(&sid[b2]);
                tma_load_3d(sb + SM_A(st), &tma_x, kk * BKF, m02, b2, sb + SMB_FULL(st));
                tma_load_3d(sb + SM_B(st), &tma_w, kk * BKF, n02, s2, sb + SMB_FULL(st));
            }
        }

        // Epilogue for tile t (TMA for the next tile already in flight)
        {
            const float* bb = bias + (size_t)s * OD + n0;
            float* yb = y + (size_t)b * NQ * OD + (size_t)m0 * OD + n0;
            #pragma unroll
            for (int mi = 0; mi < 4; mi++) {
                const int row = wm + mi * 16 + g;
                #pragma unroll
                for (int ni = 0; ni < 8; ni++) {
                    const int col = wn + ni * 8 + tg * 2;
                    const float b0v = __ldg(&bb[col]);
                    const float b1v = __ldg(&bb[col + 1]);
                    float2 v0 = make_float2(acc[mi][ni][0] + b0v, acc[mi][ni][1] + b1v);
                    float2 v1 = make_float2(acc[mi][ni][2] + b0v, acc[mi][ni][3] + b1v);
                    *reinterpret_cast<float2*>(&yb[(size_t)row * OD + col])       = v0;
                    *reinterpret_cast<float2*>(&yb[(size_t)(row + 8) * OD + col]) = v1;
                    acc[mi][ni][0] = 0.f; acc[mi][ni][1] = 0.f;
                    acc[mi][ni][2] = 0.f; acc[mi][ni][3] = 0.f;
                }
            }
        }
    }
}

// ---------------- host launch ----------------
typedef int (*PFN_encodeTiled)(
    CUtensorMap*, int, unsigned int, void*,
    const unsigned long long*, const unsigned long long*,
    const unsigned int*, const unsigned int*,
    int, int, int, int);

extern "C" void kernel_launch(void* const* d_in, const int* in_sizes, int n_in,
                              void* d_out, int out_size) {
    const float* x    = (const float*)d_in[0];
    const int*   sid  = (const int*)  d_in[1];
    const float* w    = (const float*)d_in[2];
    const float* bias = (const float*)d_in[3];
    float* y = (float*)d_out;

    PFN_encodeTiled enc = nullptr;
    cudaDriverEntryPointQueryResult qr;
    cudaGetDriverEntryPoint("cuTensorMapEncodeTiled", (void**)&enc, cudaEnableDefault, &qr);

    // Enum ABI values: FLOAT32=7, interleave NONE=0, SWIZZLE_128B=3, L2_128B=2, OOB NONE=0
    CUtensorMap tx{}, tw{};
    {
        unsigned long long dims[3]    = {HD, NQ, BATCH};
        unsigned long long strides[2] = {HD * 4ull, (unsigned long long)NQ * HD * 4ull};
        unsigned int box[3]           = {BKF, BM, 1};
        unsigned int es[3]            = {1, 1, 1};
        enc(&tx, 7, 3, (void*)x, dims, strides, box, es, 0, 3, 2, 0);
    }
    {
        unsigned long long dims[3]    = {HD, OD, NSUBJ};
        unsigned long long strides[2] = {HD * 4ull, (unsigned long long)OD * HD * 4ull};
        unsigned int box[3]           = {BKF, BN, 1};
        unsigned int es[3]            = {1, 1, 1};
        enc(&tw, 7, 3, (void*)w, dims, strides, box, es, 0, 3, 2, 0);
    }

    cudaFuncSetAttribute(scl_tf32_v13, cudaFuncAttributeMaxDynamicSharedMemorySize, SMEM_TOTAL);

    scl_tf32_v13<<<NCTA, THREADS, SMEM_TOTAL>>>(tx, tw, sid, bias, y);
}